// round 9
// baseline (speedup 1.0000x reference)
#include <cuda_runtime.h>
#include <cuda_bf16.h>
#include <cstdint>

// Problem constants (fixed by the reference)
#define B_SEG   16
#define D_F     128            // fine feature dim  (32 float4, 512 B/row)
#define D_C     256            // coarse feature dim (64 float4, 1024 B/row)
#define D_OUT   (D_C + D_F)    // 384

#define NBLK    1184           // 148 SMs x occupancy 8 = one resident wave
#define CH_C    64             // coarse rows per chunk (64 KB)
#define CH_F    128            // fine rows per chunk   (64 KB)

// Self-restoring device state (zero/NBLK at module load; finalize resets).
__device__ float        g_scratch[B_SEG * D_OUT];
__device__ unsigned int g_count = 0u;
__device__ unsigned int g_work  = NBLK;   // chunks 0..NBLK-1 are taken statically

// ---------------------------------------------------------------------------
// Persistent work-stealing segment-sum + last-block finalize (single kernel).
// Chunk id < ncg  -> coarse chunk, else fine chunk. Each chunk is a fixed
// global row range; per-chunk partial sums are independent of which CTA
// processes them (only atomic order varies).
// ---------------------------------------------------------------------------
__global__ __launch_bounds__(256, 8)
void pare_ws_kernel(const float4* __restrict__ feats_c,
                    const float4* __restrict__ feats_f,
                    const int* __restrict__ lengths_c,
                    const int* __restrict__ lengths_f,
                    float* __restrict__ out,
                    int n_c, int n_f) {
    __shared__ float4        shred[256];
    __shared__ int           scum_c[B_SEG + 1];
    __shared__ int           scum_f[B_SEG + 1];
    __shared__ unsigned int  swork;
    __shared__ bool          sdone;
    const int tid = threadIdx.x;

    if (tid == 0) {
        int ac = 0, af = 0;
        scum_c[0] = 0; scum_f[0] = 0;
#pragma unroll
        for (int i = 0; i < B_SEG; ++i) {
            ac += lengths_c[i]; scum_c[i + 1] = ac;
            af += lengths_f[i]; scum_f[i + 1] = af;
        }
    }
    __syncthreads();

    const int ncg   = n_c / CH_C;                 // coarse chunk count (512)
    const int total = ncg + (n_f + CH_F - 1) / CH_F;

    unsigned int chunk = blockIdx.x;

    while (chunk < (unsigned int)total) {
        if (chunk < (unsigned int)ncg) {
            // ---------------- coarse chunk: 64 float4 cols, 4 row lanes -----
            const int c  = tid & 63;
            const int rr = tid >> 6;
            int a = (int)chunk * CH_C;
            int b = a + CH_C; if (b > n_c) b = n_c;

            int s = 0;
            while (scum_c[s + 1] <= a) ++s;

            int g0 = a;
            while (g0 < b) {
                int e = scum_c[s + 1]; if (e > b) e = b;

                float4 acc = make_float4(0.f, 0.f, 0.f, 0.f);
                const float4* base = feats_c + c;
#pragma unroll 4
                for (int r = g0 + rr; r < e; r += 4) {
                    float4 v = __ldcs(base + (size_t)r * 64);
                    acc.x += v.x; acc.y += v.y; acc.z += v.z; acc.w += v.w;
                }

                shred[tid] = acc;
                __syncthreads();
                if (rr == 0) {
                    float4 t = shred[c];
#pragma unroll
                    for (int k = 1; k < 4; ++k) {
                        float4 v = shred[k * 64 + c];
                        t.x += v.x; t.y += v.y; t.z += v.z; t.w += v.w;
                    }
                    float* o = g_scratch + s * D_OUT + c * 4;
                    atomicAdd(o + 0, t.x);
                    atomicAdd(o + 1, t.y);
                    atomicAdd(o + 2, t.z);
                    atomicAdd(o + 3, t.w);
                }
                __syncthreads();
                if (e == scum_c[s + 1]) ++s;
                g0 = e;
            }
        } else {
            // ---------------- fine chunk: 32 float4 cols, 8 row lanes -------
            const int c  = tid & 31;
            const int rr = tid >> 5;
            int a = (int)(chunk - ncg) * CH_F;
            int b = a + CH_F; if (b > n_f) b = n_f;

            int s = 0;
            while (scum_f[s + 1] <= a) ++s;

            int g0 = a;
            while (g0 < b) {
                int e = scum_f[s + 1]; if (e > b) e = b;

                float4 acc = make_float4(0.f, 0.f, 0.f, 0.f);
                const float4* base = feats_f + c;
#pragma unroll 4
                for (int r = g0 + rr; r < e; r += 8) {
                    float4 v = __ldcs(base + (size_t)r * 32);
                    acc.x += v.x; acc.y += v.y; acc.z += v.z; acc.w += v.w;
                }

                shred[tid] = acc;
                __syncthreads();
                if (rr == 0) {
                    float4 t = shred[c];
#pragma unroll
                    for (int k = 1; k < 8; ++k) {
                        float4 v = shred[k * 32 + c];
                        t.x += v.x; t.y += v.y; t.z += v.z; t.w += v.w;
                    }
                    float* o = g_scratch + s * D_OUT + D_C + c * 4;
                    atomicAdd(o + 0, t.x);
                    atomicAdd(o + 1, t.y);
                    atomicAdd(o + 2, t.z);
                    atomicAdd(o + 3, t.w);
                }
                __syncthreads();
                if (e == scum_f[s + 1]) ++s;
                g0 = e;
            }
        }

        // steal next chunk
        if (tid == 0) swork = atomicAdd(&g_work, 1u);
        __syncthreads();
        chunk = swork;
    }

    // ---- last block to finish performs finalize + state reset ----
    if (tid == 0) {
        __threadfence();
        unsigned int old = atomicAdd(&g_count, 1u);
        sdone = (old == gridDim.x - 1);
    }
    __syncthreads();

    if (sdone) {
        __threadfence();  // make all blocks' atomics visible to this block
        for (int i = tid; i < B_SEG * D_OUT; i += 256) {
            int b = i / D_OUT;
            int d = i - b * D_OUT;
            int len = (d < D_C) ? lengths_c[b] : lengths_f[b];
            out[i] = g_scratch[i] / (float)len;
            g_scratch[i] = 0.0f;
        }
        __syncthreads();
        if (tid == 0) { g_count = 0u; g_work = NBLK; }
    }
}

// ---------------------------------------------------------------------------
extern "C" void kernel_launch(void* const* d_in, const int* in_sizes, int n_in,
                              void* d_out, int out_size) {
    const float* feats_f   = (const float*)d_in[0];   // [524288, 128]
    const float* feats_c   = (const float*)d_in[1];   // [32768, 256]
    const int*   lengths_f = (const int*)d_in[2];     // [16]
    const int*   lengths_c = (const int*)d_in[3];     // [16]
    float* out = (float*)d_out;                       // [16, 384]

    const int n_f = in_sizes[0] / D_F;   // total fine rows
    const int n_c = in_sizes[1] / D_C;   // total coarse rows

    pare_ws_kernel<<<NBLK, 256>>>((const float4*)feats_c,
                                  (const float4*)feats_f,
                                  lengths_c, lengths_f, out, n_c, n_f);
}